// round 9
// baseline (speedup 1.0000x reference)
#include <cuda_runtime.h>
#include <cuda_bf16.h>

// Problem constants (fixed by reference_code)
#define HH 768
#define WW 768
#define BB 9
#define CC 3
#define NS 100          // N_SAMPLES
#define MM 13           // offsets with dy^2+dx^2 <= 4
#define DD 27           // PATCH*PATCH*C
#define DP 28           // padded patch stride: 7 float4, rows 16B-aligned
#define NPATCH (BB * MM)            // 117
#define NTHREADS 256                // 8 warps
// Staged region: per batch, 7x7 pixels x 3 ch = 147 floats (rows contiguous)
#define RPIX 7
#define RROW (RPIX * CC)            // 21 floats per region row
#define RBAT (RPIX * RROW)          // 147 floats per batch
#define RPAD 149                    // padded per-batch stride (odd-ish, kills conflicts)
// scale = (1/T^2) / (K * B * NS) = 4 / (8*9*100); divide by counts[n] per block
#define BASE_SCALE (4.0f / (8.0f * 9.0f * 100.0f))

// Fixed-point accumulation: partial * 2^44 rounded. Integer adds commute ->
// bit-deterministic total regardless of block arrival order.
#define FIX_SCALE   1.7592186044416e13f      // 2^44
#define FIX_INV     5.684341886080802e-14    // 2^-44 (double)

// Nibble-packed offsets (value+2 per nibble), pure-ALU decode (no LDC):
// offy: -2,-1,-1,-1, 0, 0, 0, 0, 0, 1, 1, 1, 2
// offx:  0,-1, 0, 1,-2,-1, 0, 1, 2,-1, 0, 1, 0
#define OY_PACK 0x4333222221110ULL
#define OX_PACK 0x2321432103212ULL
#define OFFY(m) ((int)((OY_PACK >> (4 * (m))) & 15ULL) - 2)
#define OFFX(m) ((int)((OX_PACK >> (4 * (m))) & 15ULL) - 2)

__device__ unsigned long long g_sum  = 0ULL;  // fixed-point loss accumulator
__device__ unsigned int       g_done = 0;     // completion counter

__global__ __launch_bounds__(NTHREADS)
void fused_kernel(const float* __restrict__ latents,
                  const int*   __restrict__ anchor_idx,
                  float*       __restrict__ out) {
    __shared__ __align__(16) float sh[NPATCH * DP];   // 117 NORMALIZED patch vectors
    __shared__ float s_reg[BB * RPAD];                // staged 7x7x3 region per batch
    __shared__ int   s_valid[MM];
    __shared__ float s_wsum[NTHREADS / 32];

    const int tid  = threadIdx.x;
    const int n    = blockIdx.x;
    const int a    = __ldg(&anchor_idx[n]);
    const int ay   = a / WW;
    const int ax   = a - ay * WW;

    // --- Stage the full footprint, COALESCED: region[j][i][k][c] =
    //     latents[j][clip(ay-3+i)][clip(ax-3+k)][c].  1323 consecutive-idx
    //     elements -> consecutive GMEM addresses (row-contiguous) -> ~1-2
    //     L1tex wavefronts per warp-instruction instead of ~27.
    #pragma unroll
    for (int idx = tid; idx < BB * RBAT; idx += NTHREADS) {
        const int j = idx / RBAT;
        const int r = idx - j * RBAT;          // 0..146
        const int i = r / RROW;                // region row 0..6
        const int t = r - i * RROW;            // 0..20 (col*3 + c)
        const int yy = min(max(ay - 3 + i, 0), HH - 1);
        const int kx = t / CC;                 // region col 0..6
        const int c  = t - kx * CC;
        const int xx = min(max(ax - 3 + kx, 0), WW - 1);
        s_reg[j * RPAD + r] =
            __ldg(latents + ((size_t)j * HH + yy) * (WW * CC) + xx * CC + c);
    }

    if (tid < MM) {
        const int ny = ay + OFFY(tid);
        const int nx = ax + OFFX(tid);
        s_valid[tid] = (ny >= 0 && ny < HH && nx >= 0 && nx < WW) ? 1 : 0;
    }
    __syncthreads();

    // --- Phase 1: one thread per patch; gather 27 values from the staged
    //     region (LDS), normalize, store 7 conflict-free STS.128 (pad = 0).
    if (tid < NPATCH) {
        const int j = tid / MM;
        const int m = tid - j * MM;
        int py = ay + OFFY(m);
        int px = ax + OFFX(m);
        py = min(max(py, 0), HH - 1);          // matches jnp.clip on neighbor pos
        px = min(max(px, 0), WW - 1);

        const float* reg = &s_reg[j * RPAD];
        float v[DD];
        float ss = 0.0f;
        #pragma unroll
        for (int ky = -1; ky <= 1; ky++) {
            const int yy = min(max(py + ky, 0), HH - 1);   // edge-pad clamp
            const int ri = yy - ay + 3;                    // in [0,6]
            #pragma unroll
            for (int kx = -1; kx <= 1; kx++) {
                const int xx = min(max(px + kx, 0), WW - 1);
                const int rk = xx - ax + 3;                // in [0,6]
                const float* p = reg + ri * RROW + rk * CC;
                #pragma unroll
                for (int c = 0; c < CC; c++) {
                    const float f = p[c];
                    v[((ky + 1) * 3 + (kx + 1)) * 3 + c] = f;
                    ss += f * f;
                }
            }
        }
        const float inv = 1.0f / fmaxf(sqrtf(ss), 1e-12f);
        float4* dst = (float4*)&sh[tid * DP];
        #pragma unroll
        for (int q = 0; q < 6; q++)
            dst[q] = make_float4(v[4*q]*inv, v[4*q+1]*inv, v[4*q+2]*inv, v[4*q+3]*inv);
        dst[6] = make_float4(v[24]*inv, v[25]*inv, v[26]*inv, 0.0f);
    }
    __syncthreads();

    // --- Phase 2: lane = one neighbor vector cached in registers (7x LDS.128,
    //     conflict-free). Anchors stream as broadcast LDS.128 (uniform addr).
    //     Warps 0-3 cover b=0..3; warps 4-7 cover b=4..8.
    const int w     = tid >> 5;
    const int lane  = tid & 31;
    const int chunk = w & 3;                   // 4 chunks x 32 lanes >= 117
    const int p     = chunk * 32 + lane;       // neighbor (j,m) index
    const bool have = (p < NPATCH);
    const int pp    = have ? p : 0;
    const int j     = pp / MM;
    const int m     = pp - j * MM;
    const bool ok   = have && (s_valid[m] != 0);

    float4 v4[7];
    {
        const float4* vr = (const float4*)&sh[pp * DP];
        #pragma unroll
        for (int q = 0; q < 7; q++) v4[q] = vr[q];
    }

    const int b0 = (w < 4) ? 0 : 4;
    const int b1 = (w < 4) ? 4 : 9;
    float acc = 0.0f;
    for (int b = b0; b < b1; b++) {
        const float4* ar = (const float4*)&sh[(b * MM + 6) * DP]; // anchor = (0,0)
        float d0 = 0.0f, d1 = 0.0f, d2 = 0.0f, d3 = 0.0f;
        #pragma unroll
        for (int q = 0; q < 7; q++) {
            const float4 a4 = ar[q];           // broadcast: uniform address in warp
            d0 = fmaf(a4.x, v4[q].x, d0);
            d1 = fmaf(a4.y, v4[q].y, d1);
            d2 = fmaf(a4.z, v4[q].z, d2);
            d3 = fmaf(a4.w, v4[q].w, d3);      // pad lane: 0*0
        }
        const float d = (d0 + d1) + (d2 + d3);
        if (ok && j != b) acc += d * d;
    }

    // --- Block reduction (deterministic tree over 8 warps) ---
    #pragma unroll
    for (int o = 16; o > 0; o >>= 1)
        acc += __shfl_down_sync(0xFFFFFFFFu, acc, o);
    if (lane == 0) s_wsum[w] = acc;
    __syncthreads();

    // --- Tail: fixed-point atomic accumulation (deterministic), release-
    //     increment on the counter; last block converts and resets.
    if (w == 0 && lane == 0) {
        float s = 0.0f;
        #pragma unroll
        for (int k = 0; k < NTHREADS / 32; k++) s += s_wsum[k];
        int cnt = 0;
        #pragma unroll
        for (int mm = 0; mm < MM; mm++) cnt += s_valid[mm];
        const float partial = s * (BASE_SCALE / (float)cnt);   // >= 0
        const long long q = __float2ll_rn(partial * FIX_SCALE);
        atomicAdd(&g_sum, (unsigned long long)q);
        unsigned int prev;
        asm volatile("atom.acq_rel.gpu.add.u32 %0, [%1], %2;"
                     : "=r"(prev) : "l"(&g_done), "r"(1u) : "memory");
        if (prev == NS - 1) {
            const unsigned long long total = *(volatile unsigned long long*)&g_sum;
            out[0] = (float)((double)total * FIX_INV);
            g_sum  = 0ULL;                     // reset for next graph replay
            g_done = 0;
        }
    }
}

extern "C" void kernel_launch(void* const* d_in, const int* in_sizes, int n_in,
                              void* d_out, int out_size) {
    const float* latents    = (const float*)d_in[0];
    const int*   anchor_idx = (const int*)d_in[1];
    float*       out        = (float*)d_out;

    fused_kernel<<<NS, NTHREADS>>>(latents, anchor_idx, out);
}

// round 10
// speedup vs baseline: 1.3942x; 1.3942x over previous
#include <cuda_runtime.h>
#include <cuda_bf16.h>

// Problem constants (fixed by reference_code)
#define HH 768
#define WW 768
#define BB 9
#define CC 3
#define NS 100          // N_SAMPLES
#define MM 13           // offsets with dy^2+dx^2 <= 4
#define DD 27           // PATCH*PATCH*C
#define DP 28           // padded anchor stride: 7 float4, 16B-aligned
#define NPATCH (BB * MM)            // 117
#define NTHREADS 128                // 4 warps; thread p owns patch p (p < 117)
// scale = (1/T^2) / (K * B * NS) = 4 / (8*9*100); divide by counts[n] per block
#define BASE_SCALE (4.0f / (8.0f * 9.0f * 100.0f))

// Fixed-point packing: one u64 atomic carries BOTH the sum and the counter.
//   low 56 bits:  sum of per-anchor partials, each partial*2^44 rounded
//   high 8 bits:  completion counter (reaches 100)
// Integer adds commute -> bit-deterministic; the last arriver's return value
// already contains the complete sum (no second atomic, no acquire re-read).
#define FIX_SCALE   1.7592186044416e13f      // 2^44
#define FIX_INV     5.684341886080802e-14    // 2^-44 (double)
#define CNT_ONE     (1ULL << 56)
#define SUM_MASK    ((1ULL << 56) - 1ULL)

// Nibble-packed offsets (value+2 per nibble), pure-ALU decode (no LDC):
// offy: -2,-1,-1,-1, 0, 0, 0, 0, 0, 1, 1, 1, 2
// offx:  0,-1, 0, 1,-2,-1, 0, 1, 2,-1, 0, 1, 0
#define OY_PACK 0x4333222221110ULL
#define OX_PACK 0x2321432103212ULL
#define OFFY(m) ((int)((OY_PACK >> (4 * (m))) & 15ULL) - 2)
#define OFFX(m) ((int)((OX_PACK >> (4 * (m))) & 15ULL) - 2)

__device__ unsigned long long g_pack = 0ULL;  // {counter:8 | fixed-point sum:56}

__global__ __launch_bounds__(NTHREADS)
void fused_kernel(const float* __restrict__ latents,
                  const int*   __restrict__ anchor_idx,
                  float*       __restrict__ out) {
    __shared__ __align__(16) float sa[BB * DP];   // 9 NORMALIZED anchor vectors
    __shared__ float s_wsum[NTHREADS / 32];

    const int tid  = threadIdx.x;
    const int n    = blockIdx.x;
    const int a    = __ldg(&anchor_idx[n]);
    const int ay   = a / WW;
    const int ax   = a - ay * WW;

    // --- Each thread owns one patch (j,m); gather 27 scattered LDG (MLP=27),
    //     normalize ENTIRELY in registers. Only anchors (m==6) go to shared.
    const bool active = (tid < NPATCH);
    const int  pp  = active ? tid : 0;
    const int  j   = pp / MM;
    const int  m   = pp - j * MM;

    int py = ay + OFFY(m);
    int px = ax + OFFX(m);
    const bool valid = (py >= 0 && py < HH && px >= 0 && px < WW);
    py = min(max(py, 0), HH - 1);              // matches jnp.clip on neighbor pos
    px = min(max(px, 0), WW - 1);

    float4 v4[7];
    {
        const float* base = latents + (size_t)j * (HH * WW * CC);
        float v[DD];
        float ss = 0.0f;
        #pragma unroll
        for (int ky = -1; ky <= 1; ky++) {
            const int yy = min(max(py + ky, 0), HH - 1);   // edge-pad clamp
            #pragma unroll
            for (int kx = -1; kx <= 1; kx++) {
                const int xx = min(max(px + kx, 0), WW - 1);
                const float* p = base + ((size_t)yy * WW + xx) * CC;
                #pragma unroll
                for (int c = 0; c < CC; c++) {
                    const float f = __ldg(p + c);
                    v[((ky + 1) * 3 + (kx + 1)) * 3 + c] = f;
                    ss += f * f;
                }
            }
        }
        const float inv = 1.0f / fmaxf(sqrtf(ss), 1e-12f);
        #pragma unroll
        for (int q = 0; q < 6; q++)
            v4[q] = make_float4(v[4*q]*inv, v[4*q+1]*inv, v[4*q+2]*inv, v[4*q+3]*inv);
        v4[6] = make_float4(v[24]*inv, v[25]*inv, v[26]*inv, 0.0f);
    }

    // Publish the 9 anchor vectors (offset 6 == (0,0)) to shared.
    if (active && m == 6) {
        float4* dst = (float4*)&sa[j * DP];
        #pragma unroll
        for (int q = 0; q < 7; q++) dst[q] = v4[q];
    }
    __syncthreads();

    // --- Dot my register-resident patch against all 9 anchors (broadcast LDS,
    //     uniform address within the warp = 1 crossbar cycle per float4).
    const bool ok = active && valid;
    float acc = 0.0f;
    #pragma unroll
    for (int b = 0; b < BB; b++) {
        const float4* ar = (const float4*)&sa[b * DP];
        float d0 = 0.0f, d1 = 0.0f, d2 = 0.0f, d3 = 0.0f;
        #pragma unroll
        for (int q = 0; q < 7; q++) {
            const float4 a4 = ar[q];
            d0 = fmaf(a4.x, v4[q].x, d0);
            d1 = fmaf(a4.y, v4[q].y, d1);
            d2 = fmaf(a4.z, v4[q].z, d2);
            d3 = fmaf(a4.w, v4[q].w, d3);      // pad lane: 0*0
        }
        const float d = (d0 + d1) + (d2 + d3);
        if (ok && j != b) acc += d * d;
    }

    // --- Block reduction (deterministic tree over 4 warps) ---
    #pragma unroll
    for (int o = 16; o > 0; o >>= 1)
        acc += __shfl_down_sync(0xFFFFFFFFu, acc, o);
    if ((tid & 31) == 0) s_wsum[tid >> 5] = acc;
    __syncthreads();

    // --- Tail: ONE packed relaxed atomic. The 100th arriver's return value
    //     carries the full sum; it converts, writes out, and resets.
    if (tid == 0) {
        float s = 0.0f;
        #pragma unroll
        for (int k = 0; k < NTHREADS / 32; k++) s += s_wsum[k];
        int cnt = 0;
        #pragma unroll
        for (int mm = 0; mm < MM; mm++) {
            const int ny = ay + OFFY(mm);
            const int nx = ax + OFFX(mm);
            cnt += (ny >= 0 && ny < HH && nx >= 0 && nx < WW) ? 1 : 0;
        }
        const float partial = s * (BASE_SCALE / (float)cnt);   // >= 0, < 0.06
        const unsigned long long q =
            (unsigned long long)__float2ll_rn(partial * FIX_SCALE);
        const unsigned long long prev = atomicAdd(&g_pack, CNT_ONE | q);
        if ((prev >> 56) == NS - 1) {
            const unsigned long long total = (prev & SUM_MASK) + q;
            out[0] = (float)((double)total * FIX_INV);
            g_pack = 0ULL;                     // reset for next graph replay
        }
    }
}

extern "C" void kernel_launch(void* const* d_in, const int* in_sizes, int n_in,
                              void* d_out, int out_size) {
    const float* latents    = (const float*)d_in[0];
    const int*   anchor_idx = (const int*)d_in[1];
    float*       out        = (float*)d_out;

    fused_kernel<<<NS, NTHREADS>>>(latents, anchor_idx, out);
}

// round 11
// speedup vs baseline: 1.4010x; 1.0048x over previous
#include <cuda_runtime.h>
#include <cuda_bf16.h>

// Problem constants (fixed by reference_code)
#define HH 768
#define WW 768
#define BB 9
#define CC 3
#define NS 100          // N_SAMPLES
#define MM 13           // offsets with dy^2+dx^2 <= 4
#define DD 27           // PATCH*PATCH*C
#define DP 28           // padded anchor stride: 7 float4, 16B-aligned
#define NPATCH (BB * MM)            // 117
#define NTHREADS 128                // 4 warps; thread p owns patch p (p < 117)
// scale = (1/T^2) / (K * B * NS) = 4 / (8*9*100); divide by counts[n] per block
#define BASE_SCALE (4.0f / (8.0f * 9.0f * 100.0f))

// Fixed-point packing: one u64 atomic carries BOTH the sum and the counter.
//   low 56 bits:  sum of per-anchor partials, each partial*2^44 rounded
//   high 8 bits:  completion counter (reaches 100)
// Integer adds commute -> bit-deterministic; the last arriver's return value
// already contains the complete sum (no second atomic, no acquire re-read).
#define FIX_SCALE   1.7592186044416e13f      // 2^44
#define FIX_INV     5.684341886080802e-14    // 2^-44 (double)
#define CNT_ONE     (1ULL << 56)
#define SUM_MASK    ((1ULL << 56) - 1ULL)

// Nibble-packed offsets (value+2 per nibble), pure-ALU decode (no LDC):
// offy: -2,-1,-1,-1, 0, 0, 0, 0, 0, 1, 1, 1, 2
// offx:  0,-1, 0, 1,-2,-1, 0, 1, 2,-1, 0, 1, 0
#define OY_PACK 0x4333222221110ULL
#define OX_PACK 0x2321432103212ULL
#define OFFY(m) ((int)((OY_PACK >> (4 * (m))) & 15ULL) - 2)
#define OFFX(m) ((int)((OX_PACK >> (4 * (m))) & 15ULL) - 2)

__device__ unsigned long long g_pack = 0ULL;  // {counter:8 | fixed-point sum:56}

__global__ __launch_bounds__(NTHREADS)
void fused_kernel(const float* __restrict__ latents,
                  const int*   __restrict__ anchor_idx,
                  float*       __restrict__ out) {
    __shared__ __align__(16) float sa[BB * DP];   // 9 NORMALIZED anchor vectors
    __shared__ float s_wsum[NTHREADS / 32];

    const int tid  = threadIdx.x;
    const int n    = blockIdx.x;
    const int a    = __ldg(&anchor_idx[n]);
    const int ay   = a / WW;
    const int ax   = a - ay * WW;

    // --- Each thread owns one patch (j,m); gather 27 scattered LDG (MLP=27),
    //     normalize ENTIRELY in registers. Only anchors (m==6) go to shared.
    const bool active = (tid < NPATCH);
    const int  pp  = active ? tid : 0;
    const int  j   = pp / MM;
    const int  m   = pp - j * MM;

    int py = ay + OFFY(m);
    int px = ax + OFFX(m);
    const bool valid = (py >= 0 && py < HH && px >= 0 && px < WW);
    py = min(max(py, 0), HH - 1);              // matches jnp.clip on neighbor pos
    px = min(max(px, 0), WW - 1);

    float4 v4[7];
    {
        const float* base = latents + (size_t)j * (HH * WW * CC);
        float v[DD];
        float ss = 0.0f;
        #pragma unroll
        for (int ky = -1; ky <= 1; ky++) {
            const int yy = min(max(py + ky, 0), HH - 1);   // edge-pad clamp
            #pragma unroll
            for (int kx = -1; kx <= 1; kx++) {
                const int xx = min(max(px + kx, 0), WW - 1);
                const float* p = base + ((size_t)yy * WW + xx) * CC;
                #pragma unroll
                for (int c = 0; c < CC; c++) {
                    const float f = __ldg(p + c);
                    v[((ky + 1) * 3 + (kx + 1)) * 3 + c] = f;
                    ss += f * f;
                }
            }
        }
        const float inv = 1.0f / fmaxf(sqrtf(ss), 1e-12f);
        #pragma unroll
        for (int q = 0; q < 6; q++)
            v4[q] = make_float4(v[4*q]*inv, v[4*q+1]*inv, v[4*q+2]*inv, v[4*q+3]*inv);
        v4[6] = make_float4(v[24]*inv, v[25]*inv, v[26]*inv, 0.0f);
    }

    // Publish the 9 anchor vectors (offset 6 == (0,0)) to shared.
    if (active && m == 6) {
        float4* dst = (float4*)&sa[j * DP];
        #pragma unroll
        for (int q = 0; q < 7; q++) dst[q] = v4[q];
    }
    __syncthreads();

    // --- Dot my register-resident patch against all 9 anchors (broadcast LDS,
    //     uniform address within the warp = 1 crossbar cycle per float4).
    const bool ok = active && valid;
    float acc = 0.0f;
    #pragma unroll
    for (int b = 0; b < BB; b++) {
        const float4* ar = (const float4*)&sa[b * DP];
        float d0 = 0.0f, d1 = 0.0f, d2 = 0.0f, d3 = 0.0f;
        #pragma unroll
        for (int q = 0; q < 7; q++) {
            const float4 a4 = ar[q];
            d0 = fmaf(a4.x, v4[q].x, d0);
            d1 = fmaf(a4.y, v4[q].y, d1);
            d2 = fmaf(a4.z, v4[q].z, d2);
            d3 = fmaf(a4.w, v4[q].w, d3);      // pad lane: 0*0
        }
        const float d = (d0 + d1) + (d2 + d3);
        if (ok && j != b) acc += d * d;
    }

    // --- Block reduction (deterministic tree over 4 warps) ---
    #pragma unroll
    for (int o = 16; o > 0; o >>= 1)
        acc += __shfl_down_sync(0xFFFFFFFFu, acc, o);
    if ((tid & 31) == 0) s_wsum[tid >> 5] = acc;
    __syncthreads();

    // --- Tail: ONE packed relaxed atomic. The 100th arriver's return value
    //     carries the full sum; it converts, writes out, and resets.
    if (tid == 0) {
        float s = 0.0f;
        #pragma unroll
        for (int k = 0; k < NTHREADS / 32; k++) s += s_wsum[k];
        int cnt = 0;
        #pragma unroll
        for (int mm = 0; mm < MM; mm++) {
            const int ny = ay + OFFY(mm);
            const int nx = ax + OFFX(mm);
            cnt += (ny >= 0 && ny < HH && nx >= 0 && nx < WW) ? 1 : 0;
        }
        const float partial = s * (BASE_SCALE / (float)cnt);   // >= 0, < 0.06
        const unsigned long long q =
            (unsigned long long)__float2ll_rn(partial * FIX_SCALE);
        const unsigned long long prev = atomicAdd(&g_pack, CNT_ONE | q);
        if ((prev >> 56) == NS - 1) {
            const unsigned long long total = (prev & SUM_MASK) + q;
            out[0] = (float)((double)total * FIX_INV);
            g_pack = 0ULL;                     // reset for next graph replay
        }
    }
}

extern "C" void kernel_launch(void* const* d_in, const int* in_sizes, int n_in,
                              void* d_out, int out_size) {
    const float* latents    = (const float*)d_in[0];
    const int*   anchor_idx = (const int*)d_in[1];
    float*       out        = (float*)d_out;

    fused_kernel<<<NS, NTHREADS>>>(latents, anchor_idx, out);
}